// round 9
// baseline (speedup 1.0000x reference)
#include <cuda_runtime.h>

typedef unsigned long long u64;

#define NSTEP 256   // C2
#define NTH   128   // threads per block; thread t owns complex elements 8t..8t+7
#define SGN   0x8000000080000000ULL

// Compact coefficient streams: [step][chunk 0..11][thread], 256*12*128*16B = 6.29 MB.
// chunks 0..3:  rotA pairs 4t+0..3 (dr,di,or,oi)
// chunk  4:     (ctA[4t],stA[4t],ctA[4t+1],stA[4t+1])
// chunk  5:     (ctA[4t+2],stA[4t+2],ctA[4t+3],stA[4t+3])
// chunks 6..9:  rotB pairs 4t+0..3 (dr,di,or,oi)   (pair 4t+3 = boundary)
// chunk  10:    (ctB[4t],stB[4t],ctB[4t+1],stB[4t+1])
// chunk  11:    (ctB[4t+2],stB[4t+2],ctB[4t-1],stB[4t-1])  [zw pre-shifted]
__device__ float4 gC[NSTEP * 12 * NTH];

__device__ __forceinline__ u64 pk2(float x) {
    u64 r; asm("mov.b64 %0, {%1, %1};" : "=l"(r) : "f"(x)); return r;
}
__device__ __forceinline__ u64 pk(float lo, float hi) {
    u64 r; asm("mov.b64 %0, {%1, %2};" : "=l"(r) : "f"(lo), "f"(hi)); return r;
}
__device__ __forceinline__ void upk(u64 v, float& lo, float& hi) {
    asm("mov.b64 {%0, %1}, %2;" : "=f"(lo), "=f"(hi) : "l"(v));
}
__device__ __forceinline__ u64 mul2(u64 a, u64 b) {
    u64 r; asm("mul.rn.f32x2 %0, %1, %2;" : "=l"(r) : "l"(a), "l"(b)); return r;
}
__device__ __forceinline__ u64 fma2(u64 a, u64 b, u64 c) {
    u64 r; asm("fma.rn.f32x2 %0, %1, %2, %3;" : "=l"(r) : "l"(a), "l"(b), "l"(c)); return r;
}
__device__ __forceinline__ void st_release(unsigned* p, unsigned v) {
    asm volatile("st.release.cta.u32 [%0], %1;" :: "l"(p), "r"(v) : "memory");
}
__device__ __forceinline__ unsigned ld_acquire(unsigned* p) {
    unsigned v;
    asm volatile("ld.acquire.cta.u32 %0, [%1];" : "=r"(v) : "l"(p) : "memory");
    return v;
}

// Full local pair rotation on 2 row-groups: (f,s) -> (d*f + o*s, ct*s + st*f).
__device__ __forceinline__ void rotpair(u64* fr, u64* fi, u64* sr, u64* si,
                                        float4 cc, float ctf, float stf) {
    u64 dr = pk2(cc.x), di = pk2(cc.y), orr = pk2(cc.z), oi = pk2(cc.w);
    u64 nd = di ^ SGN, no = oi ^ SGN, ct = pk2(ctf), st = pk2(stf);
#pragma unroll
    for (int g = 0; g < 2; g++) {
        u64 ar = mul2(dr, fr[g]); ar = fma2(nd, fi[g], ar);
        ar = fma2(orr, sr[g], ar); ar = fma2(no, si[g], ar);
        u64 ai = mul2(dr, fi[g]); ai = fma2(di, fr[g], ai);
        ai = fma2(orr, si[g], ai); ai = fma2(oi, sr[g], ai);
        u64 br = mul2(ct, sr[g]); br = fma2(st, fr[g], br);
        u64 bi = mul2(ct, si[g]); bi = fma2(st, fi[g], bi);
        fr[g] = ar; fi[g] = ai; sr[g] = br; si[g] = bi;
    }
}

// phi/theta arrays: (H2=512, C2=256) row-major -> [p*256 + c]
__global__ void coeff_kernel(const float* __restrict__ phi0, const float* __restrict__ th0,
                             const float* __restrict__ phi1, const float* __restrict__ th1) {
    int idx = blockIdx.x * blockDim.x + threadIdx.x;
    if (idx >= NSTEP * 512) return;
    int p = idx & 511;     // pair index
    int c = idx >> 9;      // step
    int t = p >> 2;        // owning eunn-thread (0..127)
    int k = p & 3;         // pair slot within thread
    int base = c * 12 * NTH;
    float* F = (float*)gC;

    float sp, cp, st, ct;
    sincosf(phi0[p * NSTEP + c], &sp, &cp);
    sincosf(th0[p * NSTEP + c], &st, &ct);
    gC[base + k * NTH + t] = make_float4(cp * ct, sp * ct, -cp * st, -sp * st);
    {
        int chunk = 4 + (k >> 1), off = (k & 1) * 2;
        F[(base + chunk * NTH + t) * 4 + off]     = ct;
        F[(base + chunk * NTH + t) * 4 + off + 1] = st;
    }

    sincosf(phi1[p * NSTEP + c], &sp, &cp);
    sincosf(th1[p * NSTEP + c], &st, &ct);
    gC[base + (6 + k) * NTH + t] = make_float4(cp * ct, sp * ct, -cp * st, -sp * st);
    if (k < 2) {
        F[(base + 10 * NTH + t) * 4 + k * 2]     = ct;
        F[(base + 10 * NTH + t) * 4 + k * 2 + 1] = st;
    } else if (k == 2) {
        F[(base + 11 * NTH + t) * 4 + 0] = ct;
        F[(base + 11 * NTH + t) * 4 + 1] = st;
    } else {
        // pair 4t+3's (ct,st) is consumed as "previous pair" by thread t+1 (mod 128)
        int ts = (t + 1) & (NTH - 1);
        F[(base + 11 * NTH + ts) * 4 + 2] = ct;
        F[(base + 11 * NTH + ts) * 4 + 3] = st;
    }
}

__global__ void __launch_bounds__(NTH, 4)
eunn_kernel(const float4* __restrict__ xin, float4* __restrict__ xout) {
    const int t    = threadIdx.x;
    const int lane = t & 31;
    const int w    = t >> 5;           // 4 warps
    const int row0 = blockIdx.x * 4;   // 4 batch rows per block (2 f32x2 groups)

    u64 er[8][2], ei[8][2];
#pragma unroll
    for (int g = 0; g < 2; g++) {
        size_t r0 = (size_t)(row0 + 2 * g) * 512;
        size_t r1 = r0 + 512;
#pragma unroll
        for (int j = 0; j < 4; j++) {
            float4 a = xin[r0 + 4 * t + j];
            float4 b = xin[r1 + 4 * t + j];
            er[2 * j][g]     = pk(a.x, b.x); ei[2 * j][g]     = pk(a.y, b.y);
            er[2 * j + 1][g] = pk(a.z, b.z); ei[2 * j + 1][g] = pk(a.w, b.w);
        }
    }

    // Neighbor-handshake mailboxes. Slot ring depth 2 (adjacent-warp publish
    // skew is bounded by 1 step: publish(c) precedes consume(c) in-step, and
    // consume(c) of warp w requires publish(c) of both neighbors).
    __shared__ u64 sE0r[2][2][4], sE0i[2][2][4], sE7r[2][2][4], sE7i[2][2][4];
    __shared__ unsigned fl0[4], fl7[4];   // monotonic step flags per warp
    if (t < 4) { fl0[t] = 0; fl7[t] = 0; }
    __syncthreads();   // once, before the loop

    for (int c = 0; c < NSTEP; c++) {
        const int base = c * 12 * NTH + t;
        const int buf  = c & 1;
        float4 k0 = gC[base + 0 * NTH], k1 = gC[base + 1 * NTH];
        float4 k2 = gC[base + 2 * NTH], k3 = gC[base + 3 * NTH];
        float4 k4 = gC[base + 4 * NTH], k5 = gC[base + 5 * NTH];

        // ---- Rotation A, edge pairs first so neighbors unblock early ----
        rotpair(er[0], ei[0], er[1], ei[1], k0, k4.x, k4.y);
        if (lane == 0) {
            sE0r[buf][0][w] = er[0][0]; sE0i[buf][0][w] = ei[0][0];
            sE0r[buf][1][w] = er[0][1]; sE0i[buf][1][w] = ei[0][1];
            st_release(&fl0[w], (unsigned)(c + 1));
        }
        rotpair(er[6], ei[6], er[7], ei[7], k3, k5.z, k5.w);
        if (lane == 31) {
            sE7r[buf][0][w] = er[7][0]; sE7i[buf][0][w] = ei[7][0];
            sE7r[buf][1][w] = er[7][1]; sE7i[buf][1][w] = ei[7][1];
            st_release(&fl7[w], (unsigned)(c + 1));
        }
        rotpair(er[2], ei[2], er[3], ei[3], k1, k4.z, k4.w);
        rotpair(er[4], ei[4], er[5], ei[5], k2, k5.x, k5.y);

        // Boundary SHFLs: sources final; issue early so latency is hidden
        u64 nbr[2], nbi[2], pvr[2], pvi[2];
#pragma unroll
        for (int g = 0; g < 2; g++) {
            nbr[g] = __shfl_down_sync(0xffffffffu, er[0][g], 1);
            nbi[g] = __shfl_down_sync(0xffffffffu, ei[0][g], 1);
            pvr[g] = __shfl_up_sync(0xffffffffu, er[7][g], 1);
            pvi[g] = __shfl_up_sync(0xffffffffu, ei[7][g], 1);
        }

        // B coefficient loads (latency covered by local-B compute below)
        float4 k6 = gC[base + 6 * NTH], k7 = gC[base + 7 * NTH];
        float4 k8 = gC[base + 8 * NTH], k9 = gC[base + 9 * NTH];
        float4 kA = gC[base + 10 * NTH], kB = gC[base + 11 * NTH];

        // ---- Rotation B, local pairs (e1,e2), (e3,e4), (e5,e6) ----
        rotpair(er[1], ei[1], er[2], ei[2], k6, kA.x, kA.y);
        rotpair(er[3], ei[3], er[4], ei[4], k7, kA.z, kA.w);
        rotpair(er[5], ei[5], er[6], ei[6], k8, kB.x, kB.y);

        // ---- Rotation B, boundary pair: (e7, next-thread e0) ----
        {
            const int wn = (w + 1) & 3, wp = (w + 3) & 3;
            if (lane == 31) {
                while (ld_acquire(&fl0[wn]) < (unsigned)(c + 1)) { }
#pragma unroll
                for (int g = 0; g < 2; g++) { nbr[g] = sE0r[buf][g][wn]; nbi[g] = sE0i[buf][g][wn]; }
            }
            if (lane == 0) {
                while (ld_acquire(&fl7[wp]) < (unsigned)(c + 1)) { }
#pragma unroll
                for (int g = 0; g < 2; g++) { pvr[g] = sE7r[buf][g][wp]; pvi[g] = sE7i[buf][g][wp]; }
            }

            u64 dr = pk2(k9.x), di = pk2(k9.y), orr = pk2(k9.z), oi = pk2(k9.w);
            u64 nd = di ^ SGN, no = oi ^ SGN, ctm = pk2(kB.z), stm = pk2(kB.w);
#pragma unroll
            for (int g = 0; g < 2; g++) {
                u64 cr = mul2(dr, er[7][g]); cr = fma2(nd, ei[7][g], cr);
                cr = fma2(orr, nbr[g], cr);  cr = fma2(no, nbi[g], cr);
                u64 ci = mul2(dr, ei[7][g]); ci = fma2(di, er[7][g], ci);
                ci = fma2(orr, nbi[g], ci);  ci = fma2(oi, nbr[g], ci);
                u64 zr = mul2(ctm, er[0][g]); zr = fma2(stm, pvr[g], zr);
                u64 zi = mul2(ctm, ei[0][g]); zi = fma2(stm, pvi[g], zi);
                er[7][g] = cr; ei[7][g] = ci; er[0][g] = zr; ei[0][g] = zi;
            }
        }
    }

#pragma unroll
    for (int g = 0; g < 2; g++) {
        size_t r0 = (size_t)(row0 + 2 * g) * 512;
        size_t r1 = r0 + 512;
#pragma unroll
        for (int j = 0; j < 4; j++) {
            float4 a, b;
            upk(er[2 * j][g], a.x, b.x);     upk(ei[2 * j][g], a.y, b.y);
            upk(er[2 * j + 1][g], a.z, b.z); upk(ei[2 * j + 1][g], a.w, b.w);
            xout[r0 + 4 * t + j] = a;
            xout[r1 + 4 * t + j] = b;
        }
    }
}

extern "C" void kernel_launch(void* const* d_in, const int* in_sizes, int n_in,
                              void* d_out, int out_size) {
    const float* x    = (const float*)d_in[0];
    const float* phi0 = (const float*)d_in[1];
    const float* th0  = (const float*)d_in[2];
    const float* phi1 = (const float*)d_in[3];
    const float* th1  = (const float*)d_in[4];

    coeff_kernel<<<(NSTEP * 512 + 255) / 256, 256>>>(phi0, th0, phi1, th1);
    eunn_kernel<<<4096 / 4, NTH>>>((const float4*)x, (float4*)d_out);
}

// round 10
// speedup vs baseline: 2.2879x; 2.2879x over previous
#include <cuda_runtime.h>

typedef unsigned long long u64;

#define NSTEP 256   // C2
#define NTH   128   // threads per block; thread t owns complex elements 8t..8t+7
#define SGN   0x8000000080000000ULL

// Compact coefficient streams: [step][chunk 0..11][thread], 256*12*128*16B = 6.29 MB.
// chunks 0..3:  rotA pairs 4t+0..3 (dr,di,or,oi)
// chunk  4:     (ctA[4t],stA[4t],ctA[4t+1],stA[4t+1])
// chunk  5:     (ctA[4t+2],stA[4t+2],ctA[4t+3],stA[4t+3])
// chunks 6..9:  rotB pairs 4t+0..3 (dr,di,or,oi)   (pair 4t+3 = boundary)
// chunk  10:    (ctB[4t],stB[4t],ctB[4t+1],stB[4t+1])
// chunk  11:    (ctB[4t+2],stB[4t+2],ctB[4t-1],stB[4t-1])  [zw pre-shifted]
__device__ float4 gC[NSTEP * 12 * NTH];

__device__ __forceinline__ u64 pk2(float x) {
    u64 r; asm("mov.b64 %0, {%1, %1};" : "=l"(r) : "f"(x)); return r;
}
__device__ __forceinline__ u64 pk(float lo, float hi) {
    u64 r; asm("mov.b64 %0, {%1, %2};" : "=l"(r) : "f"(lo), "f"(hi)); return r;
}
__device__ __forceinline__ void upk(u64 v, float& lo, float& hi) {
    asm("mov.b64 {%0, %1}, %2;" : "=f"(lo), "=f"(hi) : "l"(v));
}
__device__ __forceinline__ u64 mul2(u64 a, u64 b) {
    u64 r; asm("mul.rn.f32x2 %0, %1, %2;" : "=l"(r) : "l"(a), "l"(b)); return r;
}
__device__ __forceinline__ u64 fma2(u64 a, u64 b, u64 c) {
    u64 r; asm("fma.rn.f32x2 %0, %1, %2, %3;" : "=l"(r) : "l"(a), "l"(b), "l"(c)); return r;
}

// Full local pair rotation on 2 row-groups: (f,s) -> (d*f + o*s, ct*s + st*f).
__device__ __forceinline__ void rotpair(u64* fr, u64* fi, u64* sr, u64* si,
                                        float4 cc, float ctf, float stf) {
    u64 dr = pk2(cc.x), di = pk2(cc.y), orr = pk2(cc.z), oi = pk2(cc.w);
    u64 nd = di ^ SGN, no = oi ^ SGN, ct = pk2(ctf), st = pk2(stf);
#pragma unroll
    for (int g = 0; g < 2; g++) {
        u64 ar = mul2(dr, fr[g]); ar = fma2(nd, fi[g], ar);
        ar = fma2(orr, sr[g], ar); ar = fma2(no, si[g], ar);
        u64 ai = mul2(dr, fi[g]); ai = fma2(di, fr[g], ai);
        ai = fma2(orr, si[g], ai); ai = fma2(oi, sr[g], ai);
        u64 br = mul2(ct, sr[g]); br = fma2(st, fr[g], br);
        u64 bi = mul2(ct, si[g]); bi = fma2(st, fi[g], bi);
        fr[g] = ar; fi[g] = ai; sr[g] = br; si[g] = bi;
    }
}

// phi/theta arrays: (H2=512, C2=256) row-major -> [p*256 + c]
__global__ void coeff_kernel(const float* __restrict__ phi0, const float* __restrict__ th0,
                             const float* __restrict__ phi1, const float* __restrict__ th1) {
    int idx = blockIdx.x * blockDim.x + threadIdx.x;
    if (idx >= NSTEP * 512) return;
    int p = idx & 511;     // pair index
    int c = idx >> 9;      // step
    int t = p >> 2;        // owning eunn-thread (0..127)
    int k = p & 3;         // pair slot within thread
    int base = c * 12 * NTH;
    float* F = (float*)gC;

    float sp, cp, st, ct;
    sincosf(phi0[p * NSTEP + c], &sp, &cp);
    sincosf(th0[p * NSTEP + c], &st, &ct);
    gC[base + k * NTH + t] = make_float4(cp * ct, sp * ct, -cp * st, -sp * st);
    {
        int chunk = 4 + (k >> 1), off = (k & 1) * 2;
        F[(base + chunk * NTH + t) * 4 + off]     = ct;
        F[(base + chunk * NTH + t) * 4 + off + 1] = st;
    }

    sincosf(phi1[p * NSTEP + c], &sp, &cp);
    sincosf(th1[p * NSTEP + c], &st, &ct);
    gC[base + (6 + k) * NTH + t] = make_float4(cp * ct, sp * ct, -cp * st, -sp * st);
    if (k < 2) {
        F[(base + 10 * NTH + t) * 4 + k * 2]     = ct;
        F[(base + 10 * NTH + t) * 4 + k * 2 + 1] = st;
    } else if (k == 2) {
        F[(base + 11 * NTH + t) * 4 + 0] = ct;
        F[(base + 11 * NTH + t) * 4 + 1] = st;
    } else {
        // pair 4t+3's (ct,st) is consumed as "previous pair" by thread t+1 (mod 128)
        int ts = (t + 1) & (NTH - 1);
        F[(base + 11 * NTH + ts) * 4 + 2] = ct;
        F[(base + 11 * NTH + ts) * 4 + 3] = st;
    }
}

__global__ void __launch_bounds__(NTH, 4)
eunn_kernel(const float4* __restrict__ xin, float4* __restrict__ xout) {
    const int t    = threadIdx.x;
    const int lane = t & 31;
    const int w    = t >> 5;           // 4 warps
    const int row0 = blockIdx.x * 4;   // 4 batch rows per block (2 f32x2 groups)

    u64 er[8][2], ei[8][2];
#pragma unroll
    for (int g = 0; g < 2; g++) {
        size_t r0 = (size_t)(row0 + 2 * g) * 512;
        size_t r1 = r0 + 512;
#pragma unroll
        for (int j = 0; j < 4; j++) {
            float4 a = xin[r0 + 4 * t + j];
            float4 b = xin[r1 + 4 * t + j];
            er[2 * j][g]     = pk(a.x, b.x); ei[2 * j][g]     = pk(a.y, b.y);
            er[2 * j + 1][g] = pk(a.z, b.z); ei[2 * j + 1][g] = pk(a.w, b.w);
        }
    }

    // Double-buffered warp-boundary exchange; one __syncthreads per step,
    // placed right after the edge publishes so each warp leaves the barrier
    // with ~120 f32x2 of independent work before consuming neighbor data.
    __shared__ u64 sE0r[2][2][4], sE0i[2][2][4], sE7r[2][2][4], sE7i[2][2][4];

    for (int c = 0; c < NSTEP; c++) {
        const int base = c * 12 * NTH + t;
        const int buf  = c & 1;

        // A coefficients
        float4 k0 = gC[base + 0 * NTH], k1 = gC[base + 1 * NTH];
        float4 k2 = gC[base + 2 * NTH], k3 = gC[base + 3 * NTH];
        float4 k4 = gC[base + 4 * NTH], k5 = gC[base + 5 * NTH];

        // ---- Rotation A, edge pairs first; publish immediately ----
        rotpair(er[0], ei[0], er[1], ei[1], k0, k4.x, k4.y);
        rotpair(er[6], ei[6], er[7], ei[7], k3, k5.z, k5.w);
        if (lane == 0) {
#pragma unroll
            for (int g = 0; g < 2; g++) { sE0r[buf][g][w] = er[0][g]; sE0i[buf][g][w] = ei[0][g]; }
        }
        if (lane == 31) {
#pragma unroll
            for (int g = 0; g < 2; g++) { sE7r[buf][g][w] = er[7][g]; sE7i[buf][g][w] = ei[7][g]; }
        }

        __syncthreads();   // orders publishes vs reads; all remaining work is runway

        // ---- Rotation A, middle pairs (independent of exchange) ----
        rotpair(er[2], ei[2], er[3], ei[3], k1, k4.z, k4.w);
        rotpair(er[4], ei[4], er[5], ei[5], k2, k5.x, k5.y);

        // Boundary SHFLs (sources e0/e7 are final post-A); latency hidden below
        u64 nbr[2], nbi[2], pvr[2], pvi[2];
#pragma unroll
        for (int g = 0; g < 2; g++) {
            nbr[g] = __shfl_down_sync(0xffffffffu, er[0][g], 1);
            nbi[g] = __shfl_down_sync(0xffffffffu, ei[0][g], 1);
            pvr[g] = __shfl_up_sync(0xffffffffu, er[7][g], 1);
            pvi[g] = __shfl_up_sync(0xffffffffu, ei[7][g], 1);
        }

        // B coefficients (A coeffs are dead; slots reused)
        float4 k6 = gC[base + 6 * NTH], k7 = gC[base + 7 * NTH];
        float4 k8 = gC[base + 8 * NTH], k9 = gC[base + 9 * NTH];
        float4 kA = gC[base + 10 * NTH], kB = gC[base + 11 * NTH];

        // ---- Rotation B, local pairs (e1,e2), (e3,e4), (e5,e6) ----
        rotpair(er[1], ei[1], er[2], ei[2], k6, kA.x, kA.y);
        rotpair(er[3], ei[3], er[4], ei[4], k7, kA.z, kA.w);
        rotpair(er[5], ei[5], er[6], ei[6], k8, kB.x, kB.y);

        // ---- Rotation B, boundary pair: (e7, next-thread e0) ----
        {
            const int wn = (w + 1) & 3, wp = (w + 3) & 3;
#pragma unroll
            for (int g = 0; g < 2; g++) {
                if (lane == 31) { nbr[g] = sE0r[buf][g][wn]; nbi[g] = sE0i[buf][g][wn]; }
                if (lane == 0)  { pvr[g] = sE7r[buf][g][wp]; pvi[g] = sE7i[buf][g][wp]; }
            }

            u64 dr = pk2(k9.x), di = pk2(k9.y), orr = pk2(k9.z), oi = pk2(k9.w);
            u64 nd = di ^ SGN, no = oi ^ SGN, ctm = pk2(kB.z), stm = pk2(kB.w);
#pragma unroll
            for (int g = 0; g < 2; g++) {
                u64 cr = mul2(dr, er[7][g]); cr = fma2(nd, ei[7][g], cr);
                cr = fma2(orr, nbr[g], cr);  cr = fma2(no, nbi[g], cr);
                u64 ci = mul2(dr, ei[7][g]); ci = fma2(di, er[7][g], ci);
                ci = fma2(orr, nbi[g], ci);  ci = fma2(oi, nbr[g], ci);
                u64 zr = mul2(ctm, er[0][g]); zr = fma2(stm, pvr[g], zr);
                u64 zi = mul2(ctm, ei[0][g]); zi = fma2(stm, pvi[g], zi);
                er[7][g] = cr; ei[7][g] = ci; er[0][g] = zr; ei[0][g] = zi;
            }
        }
    }

#pragma unroll
    for (int g = 0; g < 2; g++) {
        size_t r0 = (size_t)(row0 + 2 * g) * 512;
        size_t r1 = r0 + 512;
#pragma unroll
        for (int j = 0; j < 4; j++) {
            float4 a, b;
            upk(er[2 * j][g], a.x, b.x);     upk(ei[2 * j][g], a.y, b.y);
            upk(er[2 * j + 1][g], a.z, b.z); upk(ei[2 * j + 1][g], a.w, b.w);
            xout[r0 + 4 * t + j] = a;
            xout[r1 + 4 * t + j] = b;
        }
    }
}

extern "C" void kernel_launch(void* const* d_in, const int* in_sizes, int n_in,
                              void* d_out, int out_size) {
    const float* x    = (const float*)d_in[0];
    const float* phi0 = (const float*)d_in[1];
    const float* th0  = (const float*)d_in[2];
    const float* phi1 = (const float*)d_in[3];
    const float* th1  = (const float*)d_in[4];

    coeff_kernel<<<(NSTEP * 512 + 255) / 256, 256>>>(phi0, th0, phi1, th1);
    eunn_kernel<<<4096 / 4, NTH>>>((const float4*)x, (float4*)d_out);
}